// round 12
// baseline (speedup 1.0000x reference)
#include <cuda_runtime.h>
#include <math.h>

// ---------------------------------------------------------------------------
// Lookup_8710193676603: RAFT correlation pyramid lookup.
// Identity: bilinear(pool_k(corr)) == dot(f1_pix, pool_k(f2)_corner)/16.
// Round 12 = round 11 (best, 147.9us) + __launch_bounds__(256,3) on
// lookup_main: cap regs at 85 -> 3 blocks/SM -> 6 warps/SMSP for latency
// hiding of the ~190-cycle per-corner dependency chain. Single-variable test.
// ---------------------------------------------------------------------------

#define NB 4
#define NC 256
#define NP 4096

typedef unsigned long long u64;

static __device__ float g_f1t[(size_t)NB * NP * NC];   // [B,64,64,C], pre-scaled by 1/16
static __device__ float g_f2l[5570560];                 // channel-last pyramid
__device__ const int g_lvloff[4] = {0, 4194304, 5242880, 5505024};

__device__ const float g_dy[41] = {
  -4.f,
  -3.f,-3.f,-3.f,
  -2.f,-2.f,-2.f,-2.f,-2.f,
  -1.f,-1.f,-1.f,-1.f,-1.f,-1.f,-1.f,
   0.f, 0.f, 0.f, 0.f, 0.f, 0.f, 0.f, 0.f, 0.f,
   1.f, 1.f, 1.f, 1.f, 1.f, 1.f, 1.f,
   2.f, 2.f, 2.f, 2.f, 2.f,
   3.f, 3.f, 3.f,
   4.f};
__device__ const float g_dx[41] = {
   0.f,
  -1.f, 0.f, 1.f,
  -2.f,-1.f, 0.f, 1.f, 2.f,
  -3.f,-2.f,-1.f, 0.f, 1.f, 2.f, 3.f,
  -4.f,-3.f,-2.f,-1.f, 0.f, 1.f, 2.f, 3.f, 4.f,
  -3.f,-2.f,-1.f, 0.f, 1.f, 2.f, 3.f,
  -2.f,-1.f, 0.f, 1.f, 2.f,
  -1.f, 0.f, 1.f,
   0.f};

__device__ __forceinline__ u64 ffma2(u64 a, u64 b, u64 c) {
    u64 r;
    asm("fma.rn.f32x2 %0, %1, %2, %3;" : "=l"(r) : "l"(a), "l"(b), "l"(c));
    return r;
}
__device__ __forceinline__ float hadd2(u64 v) {
    float lo, hi;
    asm("mov.b64 {%0, %1}, %2;" : "=f"(lo), "=f"(hi) : "l"(v));
    return lo + hi;
}

// ---- transpose both inputs [B,C,64,64] -> [B,64,64,C] ----------------------
__global__ void transpose_both(const float* __restrict__ f1,
                               const float* __restrict__ f2,
                               float* __restrict__ o1, float* __restrict__ o2) {
    __shared__ float tile[64][65];
    int which = blockIdx.x >> 10;          // 0 -> f1 (scaled), 1 -> f2
    int bb  = blockIdx.x & 1023;
    int cc  = bb & 3;
    int i   = (bb >> 2) & 63;
    int b   = bb >> 8;
    int tid = threadIdx.x;
    const float* in  = which ? f2 : f1;
    float*       out = which ? o2 : o1;
    float scale = which ? 1.0f : (1.0f / 16.0f);
#pragma unroll
    for (int t = 0; t < 16; t++) {
        int idx = tid + t * 256;
        int cl = idx >> 6, jj = idx & 63;
        tile[cl][jj] = in[(((b * 256 + cc * 64 + cl) * 64 + i) * 64) + jj] * scale;
    }
    __syncthreads();
#pragma unroll
    for (int t = 0; t < 16; t++) {
        int idx = tid + t * 256;
        int jj = idx >> 6, cl = idx & 63;
        out[((b * 64 + i) * 64 + jj) * 256 + cc * 64 + cl] = tile[cl][jj];
    }
}

// ---- all 3 pool levels from level 0, channel-last, float4 -------------------
// outputs: lvl1 [B,32,32,C] (2x2 avg), lvl2 [B,16,16,C] (4x4), lvl3 [B,8,8,C] (8x8)
__global__ void pool_all(const float4* __restrict__ lv0, float4* __restrict__ out1,
                         float4* __restrict__ out2, float4* __restrict__ out3) {
    int idx = blockIdx.x * blockDim.x + threadIdx.x;
    int lidx, hout, win;
    float4* outp;
    if (idx < 262144)      { lidx = idx;          hout = 32; win = 2; outp = out1; }
    else if (idx < 327680) { lidx = idx - 262144; hout = 16; win = 4; outp = out2; }
    else if (idx < 344064) { lidx = idx - 327680; hout = 8;  win = 8; outp = out3; }
    else return;
    int c4 = lidx & 63;
    int r  = lidx >> 6;
    int x  = r % hout; r /= hout;
    int y  = r % hout;
    int b  = r / hout;
    float4 s = make_float4(0.f, 0.f, 0.f, 0.f);
    const float4* base = lv0 + (((size_t)(b * 64 + y * win) * 64 + x * win) * 64) + c4;
    for (int ry = 0; ry < win; ry++) {
        const float4* rp = base + (size_t)ry * 64 * 64;
        for (int rx = 0; rx < win; rx++) {
            float4 v = rp[rx * 64];
            s.x += v.x; s.y += v.y; s.z += v.z; s.w += v.w;
        }
    }
    float m = 1.0f / (float)(win * win);
    s.x *= m; s.y *= m; s.z *= m; s.w *= m;
    outp[lidx] = s;
}

// ---- main lookup: warp = 2x2 pixel group @ one level ------------------------
__global__ __launch_bounds__(256, 3) void lookup_main(const float* __restrict__ flow,
                                                      float* __restrict__ out) {
    __shared__ float sd[8][4][100];   // [warp][pixel][10x10 corner grid]
    int lane = threadIdx.x & 31;
    int warp = threadIdx.x >> 5;

    int k  = blockIdx.x >> 9;                       // level (512 blocks/level)
    int gg = ((blockIdx.x & 511) << 3) + warp;      // group id, 4096/level
    int b  = gg >> 10;
    int gy = (gg >> 5) & 31;
    int gx = gg & 31;
    int i0 = gy * 2, j0 = gx * 2;

    int   h   = 64 >> k;
    float sc  = (float)(h - 1) / (float)h;
    float inv = 1.0f / (float)(1 << k);

    // per-pixel register f1 fragments (packed f32x2 pairs) + window params
    // lane holds channels [4*lane, 4*lane+4) and [128+4*lane, 128+4*lane+4)
    ulonglong2 aL[4], aH[4];
    float ycs[4], xcs[4];            // pre-scaled centers: yc*sc, xc*sc
    int y0[4], x0[4];
    {
        int p0 = (b << 12) + (i0 << 6) + j0;
        const int dp[4] = {0, 1, 64, 65};
#pragma unroll
        for (int pp = 0; pp < 4; pp++) {
            const float* fp = g_f1t + (size_t)(p0 + dp[pp]) * 256;
            aL[pp] = *reinterpret_cast<const ulonglong2*>(fp + lane * 4);
            aH[pp] = *reinterpret_cast<const ulonglong2*>(fp + 128 + lane * 4);
        }
    }
#pragma unroll
    for (int pp = 0; pp < 4; pp++) {
        int i = i0 + (pp >> 1), j = j0 + (pp & 1);
        float fy = flow[(b * 2 + 0) * 4096 + i * 64 + j];
        float fx = flow[(b * 2 + 1) * 4096 + i * 64 + j];
        ycs[pp] = ((float)i + fy) * inv * sc;
        xcs[pp] = ((float)j + fx) * inv * sc;
        y0[pp] = (int)floorf(ycs[pp] - 4.0f * sc);
        x0[pp] = (int)floorf(xcs[pp] - 4.0f * sc);
    }

    // zero corner grids (zero padding for OOB / pruned)
    float* swf = &sd[warp][0][0];
    for (int t = lane; t < 400; t += 32) swf[t] = 0.f;
    __syncwarp();

    int uy0 = max(min(min(y0[0], y0[1]), min(y0[2], y0[3])), 0);
    int uy1 = min(max(max(y0[0], y0[1]), max(y0[2], y0[3])) + 9, h - 1);
    int ux0 = max(min(min(x0[0], x0[1]), min(x0[2], x0[3])), 0);
    int ux1 = min(max(max(x0[0], x0[1]), max(x0[2], x0[3])) + 9, h - 1);

    const float* f2base = g_f2l + g_lvloff[k] + (size_t)b * h * h * 256 + lane * 4;

    // lane's pixel for the fused reduction result: lane0->p0, 16->p1, 8->p2, 24->p3
    int myp  = ((lane & 16) ? 1 : 0) | ((lane & 8) ? 2 : 0);
    int myy0 = y0[myp], myx0 = x0[myp];
    bool amWriter = (lane & 7) == 0;
    float* mysw = &sd[warp][myp][0];

    // diamond footprint: corner read by pixel pp only if
    // |yi - ycs| + |xi - xcs| <= 4*sc + 2 (+eps)
    float R = 4.0f * sc + 2.01f;

    for (int yi = uy0; yi <= uy1; yi++) {
        // union x-interval of the 4 pixel diamonds at this row
        float xlo = 1e9f, xhi = -1e9f;
#pragma unroll
        for (int pp = 0; pp < 4; pp++) {
            float rem = R - fabsf((float)yi - ycs[pp]);
            xlo = fminf(xlo, xcs[pp] - rem);
            xhi = fmaxf(xhi, xcs[pp] + rem);
        }
        int xs = max(ux0, (int)ceilf(xlo));
        int xe = min(ux1, (int)floorf(xhi));

        const float* rowp = f2base + (size_t)yi * h * 256;
        int  myry = yi - myy0;
        bool okRow = amWriter && (unsigned)myry < 10u;
        for (int xi = xs; xi <= xe; xi++) {
            ulonglong2 bL = *reinterpret_cast<const ulonglong2*>(rowp + xi * 256);
            ulonglong2 bH = *reinterpret_cast<const ulonglong2*>(rowp + xi * 256 + 128);
            u64 c0 = ffma2(bL.x, aL[0].x, ffma2(bL.y, aL[0].y,
                     ffma2(bH.x, aH[0].x, ffma2(bH.y, aH[0].y, 0ull))));
            u64 c1 = ffma2(bL.x, aL[1].x, ffma2(bL.y, aL[1].y,
                     ffma2(bH.x, aH[1].x, ffma2(bH.y, aH[1].y, 0ull))));
            u64 c2 = ffma2(bL.x, aL[2].x, ffma2(bL.y, aL[2].y,
                     ffma2(bH.x, aH[2].x, ffma2(bH.y, aH[2].y, 0ull))));
            u64 c3 = ffma2(bL.x, aL[3].x, ffma2(bL.y, aL[3].y,
                     ffma2(bH.x, aH[3].x, ffma2(bH.y, aH[3].y, 0ull))));
            float d0 = hadd2(c0), d1 = hadd2(c1), d2 = hadd2(c2), d3 = hadd2(c3);
            // fused 4-way butterfly: results land at lanes 0(p0),16(p1),8(p2),24(p3)
            d0 += __shfl_xor_sync(0xffffffffu, d0, 16);
            d1 += __shfl_xor_sync(0xffffffffu, d1, 16);
            d2 += __shfl_xor_sync(0xffffffffu, d2, 16);
            d3 += __shfl_xor_sync(0xffffffffu, d3, 16);
            float za = (lane & 16) ? d1 : d0;
            float zb = (lane & 16) ? d3 : d2;
            za += __shfl_xor_sync(0xffffffffu, za, 8);
            zb += __shfl_xor_sync(0xffffffffu, zb, 8);
            float z = (lane & 8) ? zb : za;
            z += __shfl_xor_sync(0xffffffffu, z, 4);
            z += __shfl_xor_sync(0xffffffffu, z, 2);
            z += __shfl_xor_sync(0xffffffffu, z, 1);
            int myrx = xi - myx0;
            if (okRow && (unsigned)myrx < 10u) mysw[myry * 10 + myrx] = z;
        }
    }
    __syncwarp();

    // bilinear combine: 4 pixels x 41 samples. py = ycs + dy*sc (identity).
#pragma unroll
    for (int pp = 0; pp < 4; pp++) {
        int i = i0 + (pp >> 1), j = j0 + (pp & 1);
        int p = (b << 12) + (i << 6) + j;
        float* op = out + ((size_t)p * 4 + k) * 41;
        const float* sw = &sd[warp][pp][0];
        float ycp = ycs[pp], xcp = xcs[pp];
        int y0p = y0[pp], x0p = x0[pp];
        for (int si = lane; si < 41; si += 32) {
            float py = ycp + g_dy[si] * sc;
            float px = xcp + g_dx[si] * sc;
            float fy0 = floorf(py), fx0 = floorf(px);
            float wy1 = py - fy0, wx1 = px - fx0;
            float wy0 = 1.f - wy1, wx0 = 1.f - wx1;
            int ry = (int)fy0 - y0p;
            int rx = (int)fx0 - x0p;
            float v00 = sw[ry * 10 + rx],      v01 = sw[ry * 10 + rx + 1];
            float v10 = sw[ry * 10 + rx + 10], v11 = sw[ry * 10 + rx + 11];
            op[si] = wy0 * (wx0 * v00 + wx1 * v01) + wy1 * (wx0 * v10 + wx1 * v11);
        }
    }
}

// ---------------------------------------------------------------------------
extern "C" void kernel_launch(void* const* d_in, const int* in_sizes, int n_in,
                              void* d_out, int out_size) {
    const float* f1   = (const float*)d_in[0];
    const float* f2   = (const float*)d_in[1];
    const float* flow = (const float*)d_in[2];
    float* out = (float*)d_out;

    float *f1t_ptr, *f2l_ptr;
    cudaGetSymbolAddress((void**)&f1t_ptr, g_f1t);
    cudaGetSymbolAddress((void**)&f2l_ptr, g_f2l);

    // prep: one transpose launch (f1 scaled + f2), one pool launch (3 levels)
    transpose_both<<<2048, 256>>>(f1, f2, f1t_ptr, f2l_ptr);
    pool_all<<<1344, 256>>>((const float4*)f2l_ptr,
                            (float4*)(f2l_ptr + 4194304),
                            (float4*)(f2l_ptr + 5242880),
                            (float4*)(f2l_ptr + 5505024));

    // main: 4 levels x 512 blocks, 8 warps/block, warp = 2x2 pixel group
    lookup_main<<<2048, 256>>>(flow, out);
}

// round 13
// speedup vs baseline: 1.0943x; 1.0943x over previous
#include <cuda_runtime.h>
#include <math.h>

// ---------------------------------------------------------------------------
// Lookup_8710193676603: RAFT correlation pyramid lookup.
// Identity: bilinear(pool_k(corr)) == dot(f1_pix, pool_k(f2)_corner)/16.
// Round 13 = round 11 (best, 147.9us; plain launch bounds restored) +
// two-corner software pipelining in the xi loop: two independent
// LDG -> FFMA2 -> butterfly chains interleave, hiding the ~130-cycle
// dependent-SHFL tree latency behind the sibling corner's tree.
// ---------------------------------------------------------------------------

#define NB 4
#define NC 256
#define NP 4096

typedef unsigned long long u64;

static __device__ float g_f1t[(size_t)NB * NP * NC];   // [B,64,64,C], pre-scaled by 1/16
static __device__ float g_f2l[5570560];                 // channel-last pyramid
__device__ const int g_lvloff[4] = {0, 4194304, 5242880, 5505024};

__device__ const float g_dy[41] = {
  -4.f,
  -3.f,-3.f,-3.f,
  -2.f,-2.f,-2.f,-2.f,-2.f,
  -1.f,-1.f,-1.f,-1.f,-1.f,-1.f,-1.f,
   0.f, 0.f, 0.f, 0.f, 0.f, 0.f, 0.f, 0.f, 0.f,
   1.f, 1.f, 1.f, 1.f, 1.f, 1.f, 1.f,
   2.f, 2.f, 2.f, 2.f, 2.f,
   3.f, 3.f, 3.f,
   4.f};
__device__ const float g_dx[41] = {
   0.f,
  -1.f, 0.f, 1.f,
  -2.f,-1.f, 0.f, 1.f, 2.f,
  -3.f,-2.f,-1.f, 0.f, 1.f, 2.f, 3.f,
  -4.f,-3.f,-2.f,-1.f, 0.f, 1.f, 2.f, 3.f, 4.f,
  -3.f,-2.f,-1.f, 0.f, 1.f, 2.f, 3.f,
  -2.f,-1.f, 0.f, 1.f, 2.f,
  -1.f, 0.f, 1.f,
   0.f};

__device__ __forceinline__ u64 ffma2(u64 a, u64 b, u64 c) {
    u64 r;
    asm("fma.rn.f32x2 %0, %1, %2, %3;" : "=l"(r) : "l"(a), "l"(b), "l"(c));
    return r;
}
__device__ __forceinline__ float hadd2(u64 v) {
    float lo, hi;
    asm("mov.b64 {%0, %1}, %2;" : "=f"(lo), "=f"(hi) : "l"(v));
    return lo + hi;
}

// ---- transpose both inputs [B,C,64,64] -> [B,64,64,C] ----------------------
__global__ void transpose_both(const float* __restrict__ f1,
                               const float* __restrict__ f2,
                               float* __restrict__ o1, float* __restrict__ o2) {
    __shared__ float tile[64][65];
    int which = blockIdx.x >> 10;          // 0 -> f1 (scaled), 1 -> f2
    int bb  = blockIdx.x & 1023;
    int cc  = bb & 3;
    int i   = (bb >> 2) & 63;
    int b   = bb >> 8;
    int tid = threadIdx.x;
    const float* in  = which ? f2 : f1;
    float*       out = which ? o2 : o1;
    float scale = which ? 1.0f : (1.0f / 16.0f);
#pragma unroll
    for (int t = 0; t < 16; t++) {
        int idx = tid + t * 256;
        int cl = idx >> 6, jj = idx & 63;
        tile[cl][jj] = in[(((b * 256 + cc * 64 + cl) * 64 + i) * 64) + jj] * scale;
    }
    __syncthreads();
#pragma unroll
    for (int t = 0; t < 16; t++) {
        int idx = tid + t * 256;
        int jj = idx >> 6, cl = idx & 63;
        out[((b * 64 + i) * 64 + jj) * 256 + cc * 64 + cl] = tile[cl][jj];
    }
}

// ---- all 3 pool levels from level 0, channel-last, float4 -------------------
__global__ void pool_all(const float4* __restrict__ lv0, float4* __restrict__ out1,
                         float4* __restrict__ out2, float4* __restrict__ out3) {
    int idx = blockIdx.x * blockDim.x + threadIdx.x;
    int lidx, hout, win;
    float4* outp;
    if (idx < 262144)      { lidx = idx;          hout = 32; win = 2; outp = out1; }
    else if (idx < 327680) { lidx = idx - 262144; hout = 16; win = 4; outp = out2; }
    else if (idx < 344064) { lidx = idx - 327680; hout = 8;  win = 8; outp = out3; }
    else return;
    int c4 = lidx & 63;
    int r  = lidx >> 6;
    int x  = r % hout; r /= hout;
    int y  = r % hout;
    int b  = r / hout;
    float4 s = make_float4(0.f, 0.f, 0.f, 0.f);
    const float4* base = lv0 + (((size_t)(b * 64 + y * win) * 64 + x * win) * 64) + c4;
    for (int ry = 0; ry < win; ry++) {
        const float4* rp = base + (size_t)ry * 64 * 64;
        for (int rx = 0; rx < win; rx++) {
            float4 v = rp[rx * 64];
            s.x += v.x; s.y += v.y; s.z += v.z; s.w += v.w;
        }
    }
    float m = 1.0f / (float)(win * win);
    s.x *= m; s.y *= m; s.z *= m; s.w *= m;
    outp[lidx] = s;
}

// ---- main lookup: warp = 2x2 pixel group @ one level ------------------------
__global__ __launch_bounds__(256) void lookup_main(const float* __restrict__ flow,
                                                   float* __restrict__ out) {
    __shared__ float sd[8][4][100];   // [warp][pixel][10x10 corner grid]
    int lane = threadIdx.x & 31;
    int warp = threadIdx.x >> 5;

    int k  = blockIdx.x >> 9;                       // level (512 blocks/level)
    int gg = ((blockIdx.x & 511) << 3) + warp;      // group id, 4096/level
    int b  = gg >> 10;
    int gy = (gg >> 5) & 31;
    int gx = gg & 31;
    int i0 = gy * 2, j0 = gx * 2;

    int   h   = 64 >> k;
    float sc  = (float)(h - 1) / (float)h;
    float inv = 1.0f / (float)(1 << k);

    // per-pixel register f1 fragments (packed f32x2 pairs) + window params
    ulonglong2 aL[4], aH[4];
    float ycs[4], xcs[4];            // pre-scaled centers: yc*sc, xc*sc
    int y0[4], x0[4];
    {
        int p0 = (b << 12) + (i0 << 6) + j0;
        const int dp[4] = {0, 1, 64, 65};
#pragma unroll
        for (int pp = 0; pp < 4; pp++) {
            const float* fp = g_f1t + (size_t)(p0 + dp[pp]) * 256;
            aL[pp] = *reinterpret_cast<const ulonglong2*>(fp + lane * 4);
            aH[pp] = *reinterpret_cast<const ulonglong2*>(fp + 128 + lane * 4);
        }
    }
#pragma unroll
    for (int pp = 0; pp < 4; pp++) {
        int i = i0 + (pp >> 1), j = j0 + (pp & 1);
        float fy = flow[(b * 2 + 0) * 4096 + i * 64 + j];
        float fx = flow[(b * 2 + 1) * 4096 + i * 64 + j];
        ycs[pp] = ((float)i + fy) * inv * sc;
        xcs[pp] = ((float)j + fx) * inv * sc;
        y0[pp] = (int)floorf(ycs[pp] - 4.0f * sc);
        x0[pp] = (int)floorf(xcs[pp] - 4.0f * sc);
    }

    // zero corner grids (zero padding for OOB / pruned)
    float* swf = &sd[warp][0][0];
    for (int t = lane; t < 400; t += 32) swf[t] = 0.f;
    __syncwarp();

    int uy0 = max(min(min(y0[0], y0[1]), min(y0[2], y0[3])), 0);
    int uy1 = min(max(max(y0[0], y0[1]), max(y0[2], y0[3])) + 9, h - 1);
    int ux0 = max(min(min(x0[0], x0[1]), min(x0[2], x0[3])), 0);
    int ux1 = min(max(max(x0[0], x0[1]), max(x0[2], x0[3])) + 9, h - 1);

    const float* f2base = g_f2l + g_lvloff[k] + (size_t)b * h * h * 256 + lane * 4;

    // lane's pixel for the fused reduction result: lane0->p0, 16->p1, 8->p2, 24->p3
    int myp  = ((lane & 16) ? 1 : 0) | ((lane & 8) ? 2 : 0);
    int myy0 = y0[myp], myx0 = x0[myp];
    bool amWriter = (lane & 7) == 0;
    float* mysw = &sd[warp][myp][0];

    // diamond footprint: corner read by pixel pp only if
    // |yi - ycs| + |xi - xcs| <= 4*sc + 2 (+eps)
    float R = 4.0f * sc + 2.01f;

    for (int yi = uy0; yi <= uy1; yi++) {
        float xlo = 1e9f, xhi = -1e9f;
#pragma unroll
        for (int pp = 0; pp < 4; pp++) {
            float rem = R - fabsf((float)yi - ycs[pp]);
            xlo = fminf(xlo, xcs[pp] - rem);
            xhi = fmaxf(xhi, xcs[pp] + rem);
        }
        int xs = max(ux0, (int)ceilf(xlo));
        int xe = min(ux1, (int)floorf(xhi));

        const float* rowp = f2base + (size_t)yi * h * 256;
        int  myry = yi - myy0;
        bool okRow = amWriter && (unsigned)myry < 10u;

        int xi = xs;
        // ---- two-corner pipelined body: independent chains interleave ----
        for (; xi + 1 <= xe; xi += 2) {
            const float* cpA = rowp + xi * 256;
            const float* cpB = cpA + 256;
            ulonglong2 bLA = *reinterpret_cast<const ulonglong2*>(cpA);
            ulonglong2 bHA = *reinterpret_cast<const ulonglong2*>(cpA + 128);
            ulonglong2 bLB = *reinterpret_cast<const ulonglong2*>(cpB);
            ulonglong2 bHB = *reinterpret_cast<const ulonglong2*>(cpB + 128);

            u64 cA0 = ffma2(bLA.x, aL[0].x, ffma2(bLA.y, aL[0].y,
                      ffma2(bHA.x, aH[0].x, ffma2(bHA.y, aH[0].y, 0ull))));
            u64 cB0 = ffma2(bLB.x, aL[0].x, ffma2(bLB.y, aL[0].y,
                      ffma2(bHB.x, aH[0].x, ffma2(bHB.y, aH[0].y, 0ull))));
            u64 cA1 = ffma2(bLA.x, aL[1].x, ffma2(bLA.y, aL[1].y,
                      ffma2(bHA.x, aH[1].x, ffma2(bHA.y, aH[1].y, 0ull))));
            u64 cB1 = ffma2(bLB.x, aL[1].x, ffma2(bLB.y, aL[1].y,
                      ffma2(bHB.x, aH[1].x, ffma2(bHB.y, aH[1].y, 0ull))));
            u64 cA2 = ffma2(bLA.x, aL[2].x, ffma2(bLA.y, aL[2].y,
                      ffma2(bHA.x, aH[2].x, ffma2(bHA.y, aH[2].y, 0ull))));
            u64 cB2 = ffma2(bLB.x, aL[2].x, ffma2(bLB.y, aL[2].y,
                      ffma2(bHB.x, aH[2].x, ffma2(bHB.y, aH[2].y, 0ull))));
            u64 cA3 = ffma2(bLA.x, aL[3].x, ffma2(bLA.y, aL[3].y,
                      ffma2(bHA.x, aH[3].x, ffma2(bHA.y, aH[3].y, 0ull))));
            u64 cB3 = ffma2(bLB.x, aL[3].x, ffma2(bLB.y, aL[3].y,
                      ffma2(bHB.x, aH[3].x, ffma2(bHB.y, aH[3].y, 0ull))));

            float dA0 = hadd2(cA0), dA1 = hadd2(cA1), dA2 = hadd2(cA2), dA3 = hadd2(cA3);
            float dB0 = hadd2(cB0), dB1 = hadd2(cB1), dB2 = hadd2(cB2), dB3 = hadd2(cB3);

            // interleaved butterflies: the two trees hide each other's latency
            dA0 += __shfl_xor_sync(0xffffffffu, dA0, 16);
            dB0 += __shfl_xor_sync(0xffffffffu, dB0, 16);
            dA1 += __shfl_xor_sync(0xffffffffu, dA1, 16);
            dB1 += __shfl_xor_sync(0xffffffffu, dB1, 16);
            dA2 += __shfl_xor_sync(0xffffffffu, dA2, 16);
            dB2 += __shfl_xor_sync(0xffffffffu, dB2, 16);
            dA3 += __shfl_xor_sync(0xffffffffu, dA3, 16);
            dB3 += __shfl_xor_sync(0xffffffffu, dB3, 16);
            float zaA = (lane & 16) ? dA1 : dA0;
            float zbA = (lane & 16) ? dA3 : dA2;
            float zaB = (lane & 16) ? dB1 : dB0;
            float zbB = (lane & 16) ? dB3 : dB2;
            zaA += __shfl_xor_sync(0xffffffffu, zaA, 8);
            zaB += __shfl_xor_sync(0xffffffffu, zaB, 8);
            zbA += __shfl_xor_sync(0xffffffffu, zbA, 8);
            zbB += __shfl_xor_sync(0xffffffffu, zbB, 8);
            float zA = (lane & 8) ? zbA : zaA;
            float zB = (lane & 8) ? zbB : zaB;
            zA += __shfl_xor_sync(0xffffffffu, zA, 4);
            zB += __shfl_xor_sync(0xffffffffu, zB, 4);
            zA += __shfl_xor_sync(0xffffffffu, zA, 2);
            zB += __shfl_xor_sync(0xffffffffu, zB, 2);
            zA += __shfl_xor_sync(0xffffffffu, zA, 1);
            zB += __shfl_xor_sync(0xffffffffu, zB, 1);

            int rxA = xi - myx0;
            int rxB = rxA + 1;
            if (okRow && (unsigned)rxA < 10u) mysw[myry * 10 + rxA] = zA;
            if (okRow && (unsigned)rxB < 10u) mysw[myry * 10 + rxB] = zB;
        }
        // ---- remainder: single corner ----
        if (xi <= xe) {
            const float* cp = rowp + xi * 256;
            ulonglong2 bL = *reinterpret_cast<const ulonglong2*>(cp);
            ulonglong2 bH = *reinterpret_cast<const ulonglong2*>(cp + 128);
            u64 c0 = ffma2(bL.x, aL[0].x, ffma2(bL.y, aL[0].y,
                     ffma2(bH.x, aH[0].x, ffma2(bH.y, aH[0].y, 0ull))));
            u64 c1 = ffma2(bL.x, aL[1].x, ffma2(bL.y, aL[1].y,
                     ffma2(bH.x, aH[1].x, ffma2(bH.y, aH[1].y, 0ull))));
            u64 c2 = ffma2(bL.x, aL[2].x, ffma2(bL.y, aL[2].y,
                     ffma2(bH.x, aH[2].x, ffma2(bH.y, aH[2].y, 0ull))));
            u64 c3 = ffma2(bL.x, aL[3].x, ffma2(bL.y, aL[3].y,
                     ffma2(bH.x, aH[3].x, ffma2(bH.y, aH[3].y, 0ull))));
            float d0 = hadd2(c0), d1 = hadd2(c1), d2 = hadd2(c2), d3 = hadd2(c3);
            d0 += __shfl_xor_sync(0xffffffffu, d0, 16);
            d1 += __shfl_xor_sync(0xffffffffu, d1, 16);
            d2 += __shfl_xor_sync(0xffffffffu, d2, 16);
            d3 += __shfl_xor_sync(0xffffffffu, d3, 16);
            float za = (lane & 16) ? d1 : d0;
            float zb = (lane & 16) ? d3 : d2;
            za += __shfl_xor_sync(0xffffffffu, za, 8);
            zb += __shfl_xor_sync(0xffffffffu, zb, 8);
            float z = (lane & 8) ? zb : za;
            z += __shfl_xor_sync(0xffffffffu, z, 4);
            z += __shfl_xor_sync(0xffffffffu, z, 2);
            z += __shfl_xor_sync(0xffffffffu, z, 1);
            int myrx = xi - myx0;
            if (okRow && (unsigned)myrx < 10u) mysw[myry * 10 + myrx] = z;
        }
    }
    __syncwarp();

    // bilinear combine: 4 pixels x 41 samples. py = ycs + dy*sc (identity).
#pragma unroll
    for (int pp = 0; pp < 4; pp++) {
        int i = i0 + (pp >> 1), j = j0 + (pp & 1);
        int p = (b << 12) + (i << 6) + j;
        float* op = out + ((size_t)p * 4 + k) * 41;
        const float* sw = &sd[warp][pp][0];
        float ycp = ycs[pp], xcp = xcs[pp];
        int y0p = y0[pp], x0p = x0[pp];
        for (int si = lane; si < 41; si += 32) {
            float py = ycp + g_dy[si] * sc;
            float px = xcp + g_dx[si] * sc;
            float fy0 = floorf(py), fx0 = floorf(px);
            float wy1 = py - fy0, wx1 = px - fx0;
            float wy0 = 1.f - wy1, wx0 = 1.f - wx1;
            int ry = (int)fy0 - y0p;
            int rx = (int)fx0 - x0p;
            float v00 = sw[ry * 10 + rx],      v01 = sw[ry * 10 + rx + 1];
            float v10 = sw[ry * 10 + rx + 10], v11 = sw[ry * 10 + rx + 11];
            op[si] = wy0 * (wx0 * v00 + wx1 * v01) + wy1 * (wx0 * v10 + wx1 * v11);
        }
    }
}

// ---------------------------------------------------------------------------
extern "C" void kernel_launch(void* const* d_in, const int* in_sizes, int n_in,
                              void* d_out, int out_size) {
    const float* f1   = (const float*)d_in[0];
    const float* f2   = (const float*)d_in[1];
    const float* flow = (const float*)d_in[2];
    float* out = (float*)d_out;

    float *f1t_ptr, *f2l_ptr;
    cudaGetSymbolAddress((void**)&f1t_ptr, g_f1t);
    cudaGetSymbolAddress((void**)&f2l_ptr, g_f2l);

    transpose_both<<<2048, 256>>>(f1, f2, f1t_ptr, f2l_ptr);
    pool_all<<<1344, 256>>>((const float4*)f2l_ptr,
                            (float4*)(f2l_ptr + 4194304),
                            (float4*)(f2l_ptr + 5242880),
                            (float4*)(f2l_ptr + 5505024));

    lookup_main<<<2048, 256>>>(flow, out);
}